// round 4
// baseline (speedup 1.0000x reference)
#include <cuda_runtime.h>

// Problem constants (VectorQuantizer: z [64,32,32,256] -> [65536,256], codebook [4096,256])
#define N_ROWS  65536
#define DIM     256
#define K_CODES 4096

// ---- scratch (no allocations allowed -> __device__ globals) ----
__device__ float  g_A[N_ROWS];     // per-row sum(z^2)
__device__ float  g_C[K_CODES];    // per-code sum(e^2)
__device__ int    g_best[N_ROWS];  // argmin index per row
__device__ double g_lossAcc;       // sum of fl((q-z))^2 in double

// ============================================================================
// Kernel 0: per-row sum of squares (one warp per row, lane-strided + butterfly)
// which==0 -> g_A over z rows, which==1 -> g_C over codebook rows
// ============================================================================
__global__ void sqsum_kernel(const float* __restrict__ x, int nrows, int which) {
    int warp = (blockIdx.x * blockDim.x + threadIdx.x) >> 5;
    int lane = threadIdx.x & 31;
    if (warp >= nrows) return;
    const float* row = x + (size_t)warp * DIM;
    float s = 0.0f;
#pragma unroll
    for (int j = 0; j < DIM / 32; ++j) {
        float v = row[lane + 32 * j];
        s = fmaf(v, v, s);
    }
#pragma unroll
    for (int off = 16; off > 0; off >>= 1)
        s += __shfl_xor_sync(0xffffffffu, s, off);
    if (lane == 0) {
        if (which) g_C[warp] = s;
        else       g_A[warp] = s;
    }
}

__global__ void zero_acc_kernel() { g_lossAcc = 0.0; }

// ============================================================================
// Kernel 1: distance argmin (SGEMM-style register tiling)
//   tile: 128 rows x 128 codes, 256 threads (16x16), 8x8 micro-tile per thread
//   d = fl( fl(A - 2*t) + C ), argmin with first-index tie-break
// ============================================================================
#define BM 128
#define BN 128
#define BD 16
#define PAD 4

__global__ __launch_bounds__(256, 2)
void argmin_kernel(const float* __restrict__ z, const float* __restrict__ cb) {
    __shared__ float zs[BD][BM + PAD];   // [d][row], padded, 16B-aligned rows
    __shared__ float cs[BD][BN + PAD];   // [d][code]

    const int tid = threadIdx.x;
    const int tx  = tid & 15;
    const int ty  = tid >> 4;
    const int m0  = blockIdx.x * BM;

    float bestD[8];
    int   bestI[8];
    float Arow[8];
#pragma unroll
    for (int i = 0; i < 8; ++i) {
        int r = ((i & 4) ? 64 : 0) + ty * 4 + (i & 3);
        Arow[i]  = g_A[m0 + r];
        bestD[i] = __int_as_float(0x7f800000);  // +inf
        bestI[i] = 0x7fffffff;
    }

    for (int k0 = 0; k0 < K_CODES; k0 += BN) {
        float acc[8][8];
#pragma unroll
        for (int i = 0; i < 8; ++i)
#pragma unroll
            for (int j = 0; j < 8; ++j) acc[i][j] = 0.0f;

        for (int d0 = 0; d0 < DIM; d0 += BD) {
            // ---- load tiles (transposed into SMEM) ----
#pragma unroll
            for (int l = 0; l < 2; ++l) {
                int q  = tid + 256 * l;      // 0..511
                int r  = q >> 2;             // 0..127
                int c4 = (q & 3) * 4;        // 0,4,8,12
                float4 v = *(const float4*)(z  + (size_t)(m0 + r) * DIM + d0 + c4);
                zs[c4 + 0][r] = v.x; zs[c4 + 1][r] = v.y;
                zs[c4 + 2][r] = v.z; zs[c4 + 3][r] = v.w;
                float4 w = *(const float4*)(cb + (size_t)(k0 + r) * DIM + d0 + c4);
                cs[c4 + 0][r] = w.x; cs[c4 + 1][r] = w.y;
                cs[c4 + 2][r] = w.z; cs[c4 + 3][r] = w.w;
            }
            __syncthreads();

#pragma unroll
            for (int dd = 0; dd < BD; ++dd) {
                float4 a0 = *(const float4*)&zs[dd][ty * 4];
                float4 a1 = *(const float4*)&zs[dd][64 + ty * 4];
                float4 b0 = *(const float4*)&cs[dd][tx * 4];
                float4 b1 = *(const float4*)&cs[dd][64 + tx * 4];
                float a[8] = {a0.x, a0.y, a0.z, a0.w, a1.x, a1.y, a1.z, a1.w};
                float b[8] = {b0.x, b0.y, b0.z, b0.w, b1.x, b1.y, b1.z, b1.w};
#pragma unroll
                for (int i = 0; i < 8; ++i)
#pragma unroll
                    for (int j = 0; j < 8; ++j)
                        acc[i][j] = fmaf(a[i], b[j], acc[i][j]);
            }
            __syncthreads();
        }

        // ---- fold tile scores into running argmin (faithful fp32 rounding) ----
#pragma unroll
        for (int j = 0; j < 8; ++j) {
            int kc = k0 + ((j & 4) ? 64 : 0) + tx * 4 + (j & 3);
            float Ck = g_C[kc];
#pragma unroll
            for (int i = 0; i < 8; ++i) {
                float t2 = acc[i][j] + acc[i][j];        // exact 2*t
                float u  = __fsub_rn(Arow[i], t2);       // fl(A - 2t)
                float dq = __fadd_rn(u, Ck);             // fl(.. + C)
                if (dq < bestD[i] || (dq == bestD[i] && kc < bestI[i])) {
                    bestD[i] = dq;
                    bestI[i] = kc;
                }
            }
        }
    }

    // ---- cross-thread reduce per row (lexicographic: min d, then min idx) ----
    __syncthreads();
    float* rbd = &zs[0][0];          // 128*16 floats = 8192 B  (fits in zs)
    int*   rbi = (int*)&cs[0][0];    // 128*16 ints   = 8192 B  (fits in cs)
#pragma unroll
    for (int i = 0; i < 8; ++i) {
        int r = ((i & 4) ? 64 : 0) + ty * 4 + (i & 3);
        rbd[r * 16 + tx] = bestD[i];
        rbi[r * 16 + tx] = bestI[i];
    }
    __syncthreads();
    if (tid < BM) {
        float bd = rbd[tid * 16];
        int   bi = rbi[tid * 16];
#pragma unroll
        for (int t = 1; t < 16; ++t) {
            float d2 = rbd[tid * 16 + t];
            int   i2 = rbi[tid * 16 + t];
            if (d2 < bd || (d2 == bd && i2 < bi)) { bd = d2; bi = i2; }
        }
        g_best[m0 + tid] = bi;
    }
}

// ============================================================================
// Kernel 2: gather + straight-through output + loss partial sums
//   out = fl(z + fl(z_q - z))   (replicates reference double-rounding exactly)
//   loss accumulates fl(x)^2 with x = fl(z_q - z), summed in double
// ============================================================================
__global__ void output_kernel(const float* __restrict__ z,
                              const float* __restrict__ cb,
                              float* __restrict__ out) {
    __shared__ double ssum[256];
    double s = 0.0;
    const int total4 = N_ROWS * DIM / 4;
    const int stride = gridDim.x * blockDim.x;
    for (int i4 = blockIdx.x * blockDim.x + threadIdx.x; i4 < total4; i4 += stride) {
        int n = i4 >> 6;          // 64 float4 per row
        int c = i4 & 63;
        int best = g_best[n];
        float4 zv = ((const float4*)z)[i4];
        float4 qv = ((const float4*)cb)[best * (DIM / 4) + c];

        float x0 = __fsub_rn(qv.x, zv.x);
        float x1 = __fsub_rn(qv.y, zv.y);
        float x2 = __fsub_rn(qv.z, zv.z);
        float x3 = __fsub_rn(qv.w, zv.w);

        float4 o;
        o.x = __fadd_rn(zv.x, x0);
        o.y = __fadd_rn(zv.y, x1);
        o.z = __fadd_rn(zv.z, x2);
        o.w = __fadd_rn(zv.w, x3);
        ((float4*)out)[i4] = o;

        s += (double)__fmul_rn(x0, x0);
        s += (double)__fmul_rn(x1, x1);
        s += (double)__fmul_rn(x2, x2);
        s += (double)__fmul_rn(x3, x3);
    }
    ssum[threadIdx.x] = s;
    __syncthreads();
    for (int off = 128; off > 0; off >>= 1) {
        if (threadIdx.x < off) ssum[threadIdx.x] += ssum[threadIdx.x + off];
        __syncthreads();
    }
    if (threadIdx.x == 0) atomicAdd(&g_lossAcc, ssum[0]);
}

// ============================================================================
// Kernel 3: finalize loss = fl(m + fl(0.25*m)),  m = mean((z_q - z)^2)
// ============================================================================
__global__ void finalize_kernel(float* __restrict__ out, int out_size) {
    if (out_size > N_ROWS * DIM) {
        double m  = g_lossAcc / (double)(N_ROWS * DIM);
        float  mf = (float)m;
        out[N_ROWS * DIM] = __fadd_rn(mf, __fmul_rn(0.25f, mf));
    }
}

// ============================================================================
extern "C" void kernel_launch(void* const* d_in, const int* in_sizes, int n_in,
                              void* d_out, int out_size) {
    const float* z  = (const float*)d_in[0];
    const float* cb = (const float*)d_in[1];
    float* out = (float*)d_out;
    (void)in_sizes; (void)n_in;

    // 8 warps per 256-thread block
    sqsum_kernel<<<N_ROWS  / 8, 256>>>(z,  N_ROWS,  0);
    sqsum_kernel<<<K_CODES / 8, 256>>>(cb, K_CODES, 1);
    zero_acc_kernel<<<1, 1>>>();
    argmin_kernel<<<N_ROWS / BM, 256>>>(z, cb);
    output_kernel<<<1024, 256>>>(z, cb, out);
    finalize_kernel<<<1, 1>>>(out, out_size);
}